// round 3
// baseline (speedup 1.0000x reference)
#include <cuda_runtime.h>
#include <math.h>

#define SVOL 64000
#define BB   2
#define CC   96
#define NHD  4
#define HD   24
#define LAX  40

// ---- scratch: __device__ globals (no allocation anywhere) ----
// g_buf0: conv3 output t1  -> later x*mod
// g_buf1: folded-GEMM u    -> later attention accumulator o
__device__ float g_buf0[BB*CC*SVOL];
__device__ float g_buf1[BB*CC*SVOL];
__device__ float g_qkv [BB*288*SVOL];
__device__ float g_mu1[BB*CC], g_rs1[BB*CC], g_mu2[BB*CC], g_rs2[BB*CC];
__device__ float g_W27  [27*96*96];
__device__ float g_WcT  [96*96];
__device__ float g_bc   [96];
__device__ float g_mod2T[96*96];
__device__ float g_qkvT [96*288];
__device__ float g_projT[96*96];

__device__ __forceinline__ float gelu_f(float v){
    return 0.5f*v*(1.0f + erff(v*0.70710678118654752f));
}

// ---- weight prep ----
__global__ void prep_w27(const float* __restrict__ lp1_w){
    int tid = blockIdx.x*blockDim.x + threadIdx.x;
    if (tid < 27*96*96){
        int t = tid/(96*96); int r = tid%(96*96); int ic = r/96; int oc = r%96;
        g_W27[tid] = lp1_w[(oc*96+ic)*27 + t];
    }
}
__global__ void prep_fold(const float* __restrict__ mod1_w, const float* __restrict__ lp2_w,
                          const float* __restrict__ lp2_b, const float* __restrict__ mod1_b){
    int tid = blockIdx.x*blockDim.x + threadIdx.x;
    if (tid < 96*96){
        int k = tid/96, m = tid%96;
        float s = 0.f;
        for (int o = 0; o < 96; o++) s += mod1_w[m*96+o]*lp2_w[o*96+k];
        g_WcT[k*96+m] = s;
        if (k == 0){
            float b2 = 0.f;
            for (int o = 0; o < 96; o++) b2 += mod1_w[m*96+o]*lp2_b[o];
            g_bc[m] = b2 + mod1_b[m];
        }
    }
}
__global__ void prep_trans(const float* __restrict__ mod2_w, const float* __restrict__ qkv_w,
                           const float* __restrict__ proj_w){
    int tid = blockIdx.x*blockDim.x + threadIdx.x;
    if (tid < 96*96){
        int k = tid/96, m = tid%96;
        g_mod2T[k*96+m] = mod2_w[m*96+k];
        g_projT[k*96+m] = proj_w[m*96+k];
    }
    if (tid < 96*288){
        int k = tid/288, m = tid%288;
        g_qkvT[k*288+m] = qkv_w[m*96+k];
    }
}

// ---- conv3x3x3 circular as 27x shifted 96x96 GEMM accumulation (K chunked: 2x48) ----
__global__ __launch_bounds__(160) void conv3_kernel(const float* __restrict__ pe,
                                                    const float* __restrict__ lp1_b){
    __shared__ float Ws[48*96];   // [48 ic][96 oc]
    __shared__ float Xs[48*84];   // [48 ic][2 rows * 42 cols]
    int b = blockIdx.z, d = blockIdx.y, h0 = blockIdx.x*2;
    int tid = threadIdx.x;
    int tm = tid/10, tn = tid%10;
    float acc[6][8];
    #pragma unroll
    for (int i=0;i<6;i++)
        #pragma unroll
        for (int j=0;j<8;j++) acc[i][j]=0.f;
    const float* peb = pe + (size_t)b*CC*SVOL;
    int xoff[8];
    #pragma unroll
    for (int j=0;j<8;j++){ int col = tn*8+j; xoff[j] = (col/40)*42 + (col%40); }

    for (int dz=0; dz<3; dz++){
        int dm = d+dz-1; if (dm<0) dm+=40; if (dm>=40) dm-=40;
        for (int dy=0; dy<3; dy++){
            for (int kc=0; kc<2; kc++){
                __syncthreads();   // previous chunk's readers done
                for (int idx=tid; idx<48*84; idx+=160){
                    int icl = idx/84, cc2 = idx%84;
                    int hl = cc2/42, we = cc2%42;
                    int hh = h0+hl+dy-1; if (hh<0) hh+=40; if (hh>=40) hh-=40;
                    int ww = we-1;       if (ww<0) ww+=40; if (ww>=40) ww-=40;
                    Xs[idx] = peb[(size_t)(kc*48+icl)*SVOL + dm*1600 + hh*40 + ww];
                }
                for (int dx=0; dx<3; dx++){
                    int t = (dz*3+dy)*3+dx;
                    __syncthreads();   // Xs writes done / old Ws readers done
                    const float* wsrc = g_W27 + t*9216 + kc*48*96;
                    for (int idx=tid; idx<48*96; idx+=160) Ws[idx] = wsrc[idx];
                    __syncthreads();
                    for (int k=0;k<48;k++){
                        float wv[6], xv[8];
                        #pragma unroll
                        for (int i=0;i<6;i++) wv[i] = Ws[k*96 + tm*6 + i];
                        #pragma unroll
                        for (int j=0;j<8;j++) xv[j] = Xs[k*84 + xoff[j] + dx];
                        #pragma unroll
                        for (int i=0;i<6;i++)
                            #pragma unroll
                            for (int j=0;j<8;j++) acc[i][j] = fmaf(wv[i], xv[j], acc[i][j]);
                    }
                }
            }
        }
    }
    size_t obase = (size_t)b*CC*SVOL + d*1600;
    #pragma unroll
    for (int i=0;i<6;i++){
        int oc = tm*6+i; float bias = lp1_b[oc];
        #pragma unroll
        for (int j=0;j<8;j++){
            int col = tn*8+j; int hl = col/40, w = col%40;
            g_buf0[obase + (size_t)oc*SVOL + (h0+hl)*40 + w] = acc[i][j] + bias;
        }
    }
}

// ---- per-(b,c) instance-norm stats ----
template<int SRC, int SET>
__global__ __launch_bounds__(256) void in_stats(){
    const float* src = (SRC==0) ? g_buf0 : g_buf1;
    float* mu = (SET==1) ? g_mu1 : g_mu2;
    float* rs = (SET==1) ? g_rs1 : g_rs2;
    int bc = blockIdx.x;
    const float* p = src + (size_t)bc*SVOL;
    float s=0.f, s2=0.f;
    for (int i=threadIdx.x; i<SVOL; i+=256){ float v=p[i]; s+=v; s2=fmaf(v,v,s2); }
    __shared__ float r1[256], r2[256];
    r1[threadIdx.x]=s; r2[threadIdx.x]=s2;
    __syncthreads();
    for (int off=128; off>0; off>>=1){
        if (threadIdx.x<off){ r1[threadIdx.x]+=r1[threadIdx.x+off]; r2[threadIdx.x]+=r2[threadIdx.x+off]; }
        __syncthreads();
    }
    if (threadIdx.x==0){
        float m = r1[0]*(1.0f/SVOL);
        float var = r2[0]*(1.0f/SVOL) - m*m;
        mu[bc]=m; rs[bc]=rsqrtf(var + 1e-5f);
    }
}

// ---- fused 1x1-conv GEMM, K chunked (2x48), all-static smem ----
// PRO: 0 none, 1 = gelu(IN(x)) prologue using stats SET
// EPI: 0 none, 1 = gate * sigmoid(r)
// AW : 0 WcT, 1 mod2T, 2 qkvT, 3 projT
// SRC: 0 g_buf0, 1 g_buf1
// DST: 0 g_buf0, 1 g_buf1, 2 g_qkv, 3 external
// BIASG: 1 = g_bc, 0 = external bias arg
template<int PRO, int EPI, int AW, int SRC, int DST, int SET, int BIASG>
__global__ __launch_bounds__(256) void gemm_kernel(
    int Mtotal, float* __restrict__ extY,
    const float* __restrict__ bias_ext,
    const float* __restrict__ gate)
{
    __shared__ float As[48*96];    // [48 k][96 m]
    __shared__ float Xs[48*128];   // [48 k][128 n]
    const float* AT = (AW==0) ? g_WcT : (AW==1) ? g_mod2T : (AW==2) ? g_qkvT : g_projT;
    const float* X  = (SRC==0) ? g_buf0 : g_buf1;
    float* Y = (DST==0) ? g_buf0 : (DST==1) ? g_buf1 : (DST==2) ? g_qkv : extY;
    const float* bias = (BIASG==1) ? g_bc : bias_ext;
    const float* mu = (SET==1) ? g_mu1 : g_mu2;
    const float* rs = (SET==1) ? g_rs1 : g_rs2;

    int b = blockIdx.z, m0 = blockIdx.y*96, n0 = blockIdx.x*128;
    int tid = threadIdx.x, tm = tid>>4, tn = tid&15;
    const float* xb = X + (size_t)b*96*SVOL + n0;

    float acc[6][8];
    #pragma unroll
    for (int i=0;i<6;i++)
        #pragma unroll
        for (int j=0;j<8;j++) acc[i][j]=0.f;

    for (int kc=0; kc<2; kc++){
        __syncthreads();
        for (int idx=tid; idx<48*96; idx+=256){
            int kl = idx/96, m = idx%96;
            As[idx] = AT[(kc*48+kl)*Mtotal + m0 + m];
        }
        for (int idx=tid; idx<48*128; idx+=256){
            int kl = idx>>7, c = idx&127;
            int kg = kc*48 + kl;
            float v = xb[(size_t)kg*SVOL + c];
            if (PRO==1){ v = gelu_f((v - mu[b*96+kg]) * rs[b*96+kg]); }
            Xs[idx] = v;
        }
        __syncthreads();
        for (int k=0;k<48;k++){
            float wv[6], xv[8];
            #pragma unroll
            for (int i=0;i<6;i++) wv[i] = As[k*96 + tm*6 + i];
            #pragma unroll
            for (int j=0;j<8;j++) xv[j] = Xs[k*128 + tn*8 + j];
            #pragma unroll
            for (int i=0;i<6;i++)
                #pragma unroll
                for (int j=0;j<8;j++) acc[i][j] = fmaf(wv[i], xv[j], acc[i][j]);
        }
    }

    #pragma unroll
    for (int i=0;i<6;i++){
        int m = m0 + tm*6 + i; float bi = bias[m];
        #pragma unroll
        for (int j=0;j<8;j++){
            int col = n0 + tn*8 + j;
            float r = acc[i][j] + bi;
            if (EPI==1){
                float g = gate[((size_t)b*96 + m)*SVOL + col];
                r = g * (1.0f/(1.0f + __expf(-r)));
            }
            Y[((size_t)b*Mtotal + m)*SVOL + col] = r;
        }
    }
}

// ---- axial attention (rotation + pos_attn mathematically eliminated); out -> g_buf1 ----
template<int AXIS, bool ACCUM>
__global__ __launch_bounds__(128) void attn_kernel(){
    __shared__ float qs[HD][LAX];
    __shared__ float ks[HD][LAX];
    __shared__ float vs[LAX][HD];
    __shared__ float ps[LAX][LAX];
    int line = blockIdx.x, head = blockIdx.y, b = blockIdx.z;
    int tid = threadIdx.x;
    int s0 = 0, stride = 1;
    if (AXIS==0){ int d=line/40, h=line%40; s0 = d*1600 + h*40; stride = 1;    }
    if (AXIS==1){ int d=line/40, w=line%40; s0 = d*1600 + w;    stride = 40;   }
    if (AXIS==2){ int h=line/40, w=line%40; s0 = h*40 + w;      stride = 1600; }
    const float* base = g_qkv + (size_t)b*288*SVOL;

    for (int idx=tid; idx<2*HD*LAX; idx+=128){
        int t = idx/960, r = idx%960, hd = r/40, l = r%40;
        float v = base[(size_t)((t*NHD+head)*HD + hd)*SVOL + s0 + l*stride];
        if (t==0) qs[hd][l]=v; else ks[hd][l]=v;
    }
    for (int idx=tid; idx<HD*LAX; idx+=128){
        int hd = idx/40, l = idx%40;
        vs[l][hd] = base[(size_t)((2*NHD+head)*HD + hd)*SVOL + s0 + l*stride];
    }
    __syncthreads();

    const float scale = 0.2041241452319315f;  // 24^-0.5
    for (int idx=tid; idx<400; idx+=128){
        int i = idx/10, j0 = (idx%10)*4;
        float a0=0.f,a1=0.f,a2=0.f,a3=0.f;
        #pragma unroll
        for (int hd=0; hd<HD; hd++){
            float qv = qs[hd][i];
            float4 kv = *reinterpret_cast<const float4*>(&ks[hd][j0]);
            a0 = fmaf(qv,kv.x,a0); a1 = fmaf(qv,kv.y,a1);
            a2 = fmaf(qv,kv.z,a2); a3 = fmaf(qv,kv.w,a3);
        }
        ps[i][j0+0]=a0*scale; ps[i][j0+1]=a1*scale;
        ps[i][j0+2]=a2*scale; ps[i][j0+3]=a3*scale;
    }
    __syncthreads();
    if (tid < 40){
        float mx = -1e30f;
        for (int j=0;j<40;j++) mx = fmaxf(mx, ps[tid][j]);
        float sum = 0.f;
        for (int j=0;j<40;j++){ float e = __expf(ps[tid][j]-mx); ps[tid][j]=e; sum+=e; }
        float inv = 1.0f/sum;
        for (int j=0;j<40;j++) ps[tid][j]*=inv;
    }
    __syncthreads();
    for (int idx=tid; idx<240; idx+=128){
        int i = idx/6, hd0 = (idx%6)*4;
        float a0=0.f,a1=0.f,a2=0.f,a3=0.f;
        #pragma unroll
        for (int j=0;j<40;j++){
            float pv = ps[i][j];
            float4 vv = *reinterpret_cast<const float4*>(&vs[j][hd0]);
            a0 = fmaf(pv,vv.x,a0); a1 = fmaf(pv,vv.y,a1);
            a2 = fmaf(pv,vv.z,a2); a3 = fmaf(pv,vv.w,a3);
        }
        float r[4] = {a0,a1,a2,a3};
        #pragma unroll
        for (int q=0;q<4;q++){
            size_t oi = ((size_t)b*CC + head*HD + hd0 + q)*SVOL + s0 + i*stride;
            if (ACCUM) g_buf1[oi] += r[q]; else g_buf1[oi] = r[q];
        }
    }
}

extern "C" void kernel_launch(void* const* d_in, const int* in_sizes, int n_in,
                              void* d_out, int out_size){
    const float* x     = (const float*)d_in[0];
    const float* pe    = (const float*)d_in[1];
    const float* qkv_w = (const float*)d_in[2];
    const float* qkv_b = (const float*)d_in[3];
    const float* lp1_w = (const float*)d_in[4];
    const float* lp1_b = (const float*)d_in[5];
    const float* lp2_w = (const float*)d_in[6];
    const float* lp2_b = (const float*)d_in[7];
    const float* mod1_w= (const float*)d_in[8];
    const float* mod1_b= (const float*)d_in[9];
    const float* mod2_w= (const float*)d_in[10];
    const float* mod2_b= (const float*)d_in[11];
    // d_in[12..16] (pa_w, pa_b, R6_d/h/w) are mathematically dead:
    //   pos_attn adds a per-row constant under softmax; R is orthogonal so q.k is invariant.
    const float* proj_w= (const float*)d_in[17];
    const float* proj_b= (const float*)d_in[18];
    float* out = (float*)d_out;

    prep_w27 <<<(27*96*96+255)/256, 256>>>(lp1_w);
    prep_fold<<<(96*96+255)/256,    256>>>(mod1_w, lp2_w, lp2_b, mod1_b);
    prep_trans<<<(96*288+255)/256,  256>>>(mod2_w, qkv_w, proj_w);

    // t1 = conv3(pos_emb) -> buf0
    conv3_kernel<<<dim3(20,40,BB), 160>>>(pe, lp1_b);
    in_stats<0,1><<<BB*CC, 256>>>();
    // u = Wc @ gelu(IN(t1)) + bc -> buf1
    gemm_kernel<1,0,0,0,1,1,1><<<dim3(500,1,BB), 256>>>(96, nullptr, nullptr, nullptr);
    in_stats<1,2><<<BB*CC, 256>>>();
    // xm = x * sigmoid(mod2 @ gelu(IN(u)) + b) -> buf0 (t1 dead)
    gemm_kernel<1,1,1,1,0,2,0><<<dim3(500,1,BB), 256>>>(96, nullptr, mod2_b, x);
    // qkv = qkv_w @ xm + qkv_b
    gemm_kernel<0,0,2,0,2,0,0><<<dim3(500,3,BB), 256>>>(288, nullptr, qkv_b, nullptr);
    // axial attention, accumulate into buf1 (u dead)
    attn_kernel<0,false><<<dim3(1600,NHD,BB), 128>>>();
    attn_kernel<1,true ><<<dim3(1600,NHD,BB), 128>>>();
    attn_kernel<2,true ><<<dim3(1600,NHD,BB), 128>>>();
    // out = proj @ o + proj_b
    gemm_kernel<0,0,3,1,3,0,0><<<dim3(500,1,BB), 256>>>(96, out, proj_b, nullptr);
}

// round 4
// speedup vs baseline: 1.0415x; 1.0415x over previous
#include <cuda_runtime.h>
#include <math.h>

#define SVOL 64000
#define BB   2
#define CC   96
#define NHD  4
#define HD   24
#define LAX  40

// ---- scratch: __device__ globals (no allocation anywhere) ----
// g_buf0: conv3 output t1  -> later x*mod
// g_buf1: folded-GEMM u    -> later attention accumulator o
__device__ float g_buf0[BB*CC*SVOL];
__device__ float g_buf1[BB*CC*SVOL];
__device__ float g_qkv [BB*288*SVOL];
__device__ float g_mu1[BB*CC], g_rs1[BB*CC], g_mu2[BB*CC], g_rs2[BB*CC];
__device__ float g_W27  [27*96*96];
__device__ float g_WcT  [96*96];
__device__ float g_bc   [96];
__device__ float g_mod2T[96*96];
__device__ float g_qkvT [96*288];
__device__ float g_projT[96*96];

__device__ __forceinline__ float gelu_f(float v){
    return 0.5f*v*(1.0f + erff(v*0.70710678118654752f));
}

// ---- weight prep ----
__global__ void prep_w27(const float* __restrict__ lp1_w){
    int tid = blockIdx.x*blockDim.x + threadIdx.x;
    if (tid < 27*96*96){
        int t = tid/(96*96); int r = tid%(96*96); int ic = r/96; int oc = r%96;
        g_W27[tid] = lp1_w[(oc*96+ic)*27 + t];
    }
}
__global__ void prep_fold(const float* __restrict__ mod1_w, const float* __restrict__ lp2_w,
                          const float* __restrict__ lp2_b, const float* __restrict__ mod1_b){
    int tid = blockIdx.x*blockDim.x + threadIdx.x;
    if (tid < 96*96){
        int k = tid/96, m = tid%96;
        float s = 0.f;
        for (int o = 0; o < 96; o++) s += mod1_w[m*96+o]*lp2_w[o*96+k];
        g_WcT[k*96+m] = s;
        if (k == 0){
            float b2 = 0.f;
            for (int o = 0; o < 96; o++) b2 += mod1_w[m*96+o]*lp2_b[o];
            g_bc[m] = b2 + mod1_b[m];
        }
    }
}
__global__ void prep_trans(const float* __restrict__ mod2_w, const float* __restrict__ qkv_w,
                           const float* __restrict__ proj_w){
    int tid = blockIdx.x*blockDim.x + threadIdx.x;
    if (tid < 96*96){
        int k = tid/96, m = tid%96;
        g_mod2T[k*96+m] = mod2_w[m*96+k];
        g_projT[k*96+m] = proj_w[m*96+k];
    }
    if (tid < 96*288){
        int k = tid/288, m = tid%288;
        g_qkvT[k*288+m] = qkv_w[m*96+k];
    }
}

// ---- conv3x3x3 circular: 8oc x 10col micro-tile, 3 dx weight slices resident ----
// smem: Xs[32][84] + Ws3[3][32][96] = 10752 + 36864 = 47616 B (fits static 48KB)
__global__ __launch_bounds__(96) void conv3_kernel(const float* __restrict__ pe,
                                                   const float* __restrict__ lp1_b){
    __shared__ float Xs [32*84];       // [32 ic][2 rows * 42 padded cols]
    __shared__ float Ws3[3*32*96];     // [dx][32 ic][96 oc]
    int b = blockIdx.z, d = blockIdx.y, h0 = blockIdx.x*2;
    int tid = threadIdx.x;
    int tm = tid/8, tn = tid%8;        // tm 0..11 (oc), tn 0..7 (col group of 10)
    int cb = tn*10;                    // base col 0..70
    int g  = cb/40;                    // row within 2-row tile
    int off0 = g*42 + (cb%40);         // offset of col cb's (dx=0 -> col-1) halo start

    float acc[8][10];
    #pragma unroll
    for (int i=0;i<8;i++)
        #pragma unroll
        for (int j=0;j<10;j++) acc[i][j]=0.f;

    const float* peb = pe + (size_t)b*CC*SVOL;

    for (int dz=0; dz<3; dz++){
        int dm = d+dz-1; if (dm<0) dm+=40; if (dm>=40) dm-=40;
        for (int dy=0; dy<3; dy++){
            int t0 = (dz*3+dy)*3;
            for (int kc=0; kc<3; kc++){
                __syncthreads();   // previous chunk readers done
                // stage Xs: 32 ic x 84
                for (int idx=tid; idx<32*84; idx+=96){
                    int icl = idx/84, cc2 = idx%84;
                    int hl = cc2/42, we = cc2%42;
                    int hh = h0+hl+dy-1; if (hh<0) hh+=40; if (hh>=40) hh-=40;
                    int ww = we-1;       if (ww<0) ww+=40; if (ww>=40) ww-=40;
                    Xs[idx] = peb[(size_t)(kc*32+icl)*SVOL + dm*1600 + hh*40 + ww];
                }
                // stage Ws3: 3 x 32 x 96 floats as float4 (2304 float4)
                {
                    const float* wbase = g_W27 + (size_t)t0*9216 + kc*32*96;
                    for (int idx=tid; idx<2304; idx+=96){
                        int dx = idx/768, r = idx%768;   // r over 32*24 float4
                        *reinterpret_cast<float4*>(&Ws3[dx*3072 + r*4]) =
                            *reinterpret_cast<const float4*>(&wbase[dx*9216 + r*4]);
                    }
                }
                __syncthreads();
                for (int k=0;k<32;k++){
                    float xl[12];
                    #pragma unroll
                    for (int l=0;l<12;l++) xl[l] = Xs[k*84 + off0 + l];
                    #pragma unroll
                    for (int dx=0; dx<3; dx++){
                        float4 w0 = *reinterpret_cast<const float4*>(&Ws3[dx*3072 + k*96 + tm*8]);
                        float4 w1 = *reinterpret_cast<const float4*>(&Ws3[dx*3072 + k*96 + tm*8 + 4]);
                        float wv[8] = {w0.x,w0.y,w0.z,w0.w,w1.x,w1.y,w1.z,w1.w};
                        #pragma unroll
                        for (int i=0;i<8;i++)
                            #pragma unroll
                            for (int j=0;j<10;j++)
                                acc[i][j] = fmaf(wv[i], xl[j+dx], acc[i][j]);
                    }
                }
            }
        }
    }
    size_t obase = (size_t)b*CC*SVOL + d*1600 + (h0+g)*40 + (cb%40);
    #pragma unroll
    for (int i=0;i<8;i++){
        int oc = tm*8+i; float bias = lp1_b[oc];
        #pragma unroll
        for (int j=0;j<10;j++)
            g_buf0[obase + (size_t)oc*SVOL + j] = acc[i][j] + bias;
    }
}

// ---- per-(b,c) instance-norm stats ----
template<int SRC, int SET>
__global__ __launch_bounds__(256) void in_stats(){
    const float* src = (SRC==0) ? g_buf0 : g_buf1;
    float* mu = (SET==1) ? g_mu1 : g_mu2;
    float* rs = (SET==1) ? g_rs1 : g_rs2;
    int bc = blockIdx.x;
    const float* p = src + (size_t)bc*SVOL;
    float s=0.f, s2=0.f;
    for (int i=threadIdx.x; i<SVOL/4; i+=256){
        float4 v = reinterpret_cast<const float4*>(p)[i];
        s += v.x+v.y+v.z+v.w;
        s2 = fmaf(v.x,v.x,s2); s2 = fmaf(v.y,v.y,s2);
        s2 = fmaf(v.z,v.z,s2); s2 = fmaf(v.w,v.w,s2);
    }
    __shared__ float r1[256], r2[256];
    r1[threadIdx.x]=s; r2[threadIdx.x]=s2;
    __syncthreads();
    for (int off=128; off>0; off>>=1){
        if (threadIdx.x<off){ r1[threadIdx.x]+=r1[threadIdx.x+off]; r2[threadIdx.x]+=r2[threadIdx.x+off]; }
        __syncthreads();
    }
    if (threadIdx.x==0){
        float m = r1[0]*(1.0f/SVOL);
        float var = r2[0]*(1.0f/SVOL) - m*m;
        mu[bc]=m; rs[bc]=rsqrtf(var + 1e-5f);
    }
}

// ---- fused 1x1-conv GEMM: 8x8 micro-tile, all-float4 shared loads ----
// PRO: 1 = gelu(IN(x)) prologue using stats SET; EPI: 1 = gate * sigmoid(r)
// AW: 0 WcT 1 mod2T 2 qkvT 3 projT; SRC: 0 buf0 1 buf1; DST: 0 buf0 1 buf1 2 qkv 3 ext
template<int PRO, int EPI, int AW, int SRC, int DST, int SET, int BIASG>
__global__ __launch_bounds__(192) void gemm_kernel(
    int Mtotal, float* __restrict__ extY,
    const float* __restrict__ bias_ext,
    const float* __restrict__ gate)
{
    __shared__ float As[48*96];    // [48 k][96 m]
    __shared__ float Xs[48*128];   // [48 k][128 n]
    const float* AT = (AW==0) ? g_WcT : (AW==1) ? g_mod2T : (AW==2) ? g_qkvT : g_projT;
    const float* X  = (SRC==0) ? g_buf0 : g_buf1;
    float* Y = (DST==0) ? g_buf0 : (DST==1) ? g_buf1 : (DST==2) ? g_qkv : extY;
    const float* bias = (BIASG==1) ? g_bc : bias_ext;
    const float* mu = (SET==1) ? g_mu1 : g_mu2;
    const float* rs = (SET==1) ? g_rs1 : g_rs2;

    int b = blockIdx.z, m0 = blockIdx.y*96, n0 = blockIdx.x*128;
    int tid = threadIdx.x, tm = tid/16, tn = tid%16;   // 12 x 16
    const float* xb = X + (size_t)b*96*SVOL + n0;

    float acc[8][8];
    #pragma unroll
    for (int i=0;i<8;i++)
        #pragma unroll
        for (int j=0;j<8;j++) acc[i][j]=0.f;

    for (int kc=0; kc<2; kc++){
        __syncthreads();
        // As: 48*24 float4
        for (int idx=tid; idx<1152; idx+=192){
            int k = idx/24, mq = idx%24;
            *reinterpret_cast<float4*>(&As[k*96 + mq*4]) =
                *reinterpret_cast<const float4*>(&AT[(kc*48+k)*Mtotal + m0 + mq*4]);
        }
        // Xs: 48*32 float4 (+ optional IN+gelu)
        for (int idx=tid; idx<1536; idx+=192){
            int k = idx/32, cq = idx%32;
            int kg = kc*48 + k;
            float4 v = *reinterpret_cast<const float4*>(&xb[(size_t)kg*SVOL + cq*4]);
            if (PRO==1){
                float m = mu[b*96+kg], r = rs[b*96+kg];
                v.x = gelu_f((v.x-m)*r); v.y = gelu_f((v.y-m)*r);
                v.z = gelu_f((v.z-m)*r); v.w = gelu_f((v.w-m)*r);
            }
            *reinterpret_cast<float4*>(&Xs[k*128 + cq*4]) = v;
        }
        __syncthreads();
        for (int k=0;k<48;k++){
            float4 w0 = *reinterpret_cast<const float4*>(&As[k*96 + tm*8]);
            float4 w1 = *reinterpret_cast<const float4*>(&As[k*96 + tm*8 + 4]);
            float4 x0 = *reinterpret_cast<const float4*>(&Xs[k*128 + tn*8]);
            float4 x1 = *reinterpret_cast<const float4*>(&Xs[k*128 + tn*8 + 4]);
            float wv[8] = {w0.x,w0.y,w0.z,w0.w,w1.x,w1.y,w1.z,w1.w};
            float xv[8] = {x0.x,x0.y,x0.z,x0.w,x1.x,x1.y,x1.z,x1.w};
            #pragma unroll
            for (int i=0;i<8;i++)
                #pragma unroll
                for (int j=0;j<8;j++) acc[i][j] = fmaf(wv[i], xv[j], acc[i][j]);
        }
    }

    #pragma unroll
    for (int i=0;i<8;i++){
        int m = m0 + tm*8 + i; float bi = bias[m];
        #pragma unroll
        for (int j=0;j<8;j++){
            int col = n0 + tn*8 + j;
            float r = acc[i][j] + bi;
            if (EPI==1){
                float gv = gate[((size_t)b*96 + m)*SVOL + col];
                r = gv * (1.0f/(1.0f + __expf(-r)));
            }
            Y[((size_t)b*Mtotal + m)*SVOL + col] = r;
        }
    }
}

// ---- axial attention (rotation + pos_attn mathematically eliminated); out -> g_buf1 ----
template<int AXIS, bool ACCUM>
__global__ __launch_bounds__(128) void attn_kernel(){
    __shared__ float qs[HD][LAX];
    __shared__ float ks[HD][LAX];
    __shared__ float vs[LAX][HD];
    __shared__ float ps[LAX][LAX];
    int line = blockIdx.x, head = blockIdx.y, b = blockIdx.z;
    int tid = threadIdx.x;
    int s0 = 0, stride = 1;
    if (AXIS==0){ int d=line/40, h=line%40; s0 = d*1600 + h*40; stride = 1;    }
    if (AXIS==1){ int d=line/40, w=line%40; s0 = d*1600 + w;    stride = 40;   }
    if (AXIS==2){ int h=line/40, w=line%40; s0 = h*40 + w;      stride = 1600; }
    const float* base = g_qkv + (size_t)b*288*SVOL;

    for (int idx=tid; idx<2*HD*LAX; idx+=128){
        int t = idx/960, r = idx%960, hd = r/40, l = r%40;
        float v = base[(size_t)((t*NHD+head)*HD + hd)*SVOL + s0 + l*stride];
        if (t==0) qs[hd][l]=v; else ks[hd][l]=v;
    }
    for (int idx=tid; idx<HD*LAX; idx+=128){
        int hd = idx/40, l = idx%40;
        vs[l][hd] = base[(size_t)((2*NHD+head)*HD + hd)*SVOL + s0 + l*stride];
    }
    __syncthreads();

    const float scale = 0.2041241452319315f;  // 24^-0.5
    for (int idx=tid; idx<400; idx+=128){
        int i = idx/10, j0 = (idx%10)*4;
        float a0=0.f,a1=0.f,a2=0.f,a3=0.f;
        #pragma unroll
        for (int hd=0; hd<HD; hd++){
            float qv = qs[hd][i];
            float4 kv = *reinterpret_cast<const float4*>(&ks[hd][j0]);
            a0 = fmaf(qv,kv.x,a0); a1 = fmaf(qv,kv.y,a1);
            a2 = fmaf(qv,kv.z,a2); a3 = fmaf(qv,kv.w,a3);
        }
        ps[i][j0+0]=a0*scale; ps[i][j0+1]=a1*scale;
        ps[i][j0+2]=a2*scale; ps[i][j0+3]=a3*scale;
    }
    __syncthreads();
    if (tid < 40){
        float mx = -1e30f;
        for (int j=0;j<40;j++) mx = fmaxf(mx, ps[tid][j]);
        float sum = 0.f;
        for (int j=0;j<40;j++){ float e = __expf(ps[tid][j]-mx); ps[tid][j]=e; sum+=e; }
        float inv = 1.0f/sum;
        for (int j=0;j<40;j++) ps[tid][j]*=inv;
    }
    __syncthreads();
    for (int idx=tid; idx<240; idx+=128){
        int i = idx/6, hd0 = (idx%6)*4;
        float a0=0.f,a1=0.f,a2=0.f,a3=0.f;
        #pragma unroll
        for (int j=0;j<40;j++){
            float pv = ps[i][j];
            float4 vv = *reinterpret_cast<const float4*>(&vs[j][hd0]);
            a0 = fmaf(pv,vv.x,a0); a1 = fmaf(pv,vv.y,a1);
            a2 = fmaf(pv,vv.z,a2); a3 = fmaf(pv,vv.w,a3);
        }
        float r[4] = {a0,a1,a2,a3};
        #pragma unroll
        for (int q=0;q<4;q++){
            size_t oi = ((size_t)b*CC + head*HD + hd0 + q)*SVOL + s0 + i*stride;
            if (ACCUM) g_buf1[oi] += r[q]; else g_buf1[oi] = r[q];
        }
    }
}

extern "C" void kernel_launch(void* const* d_in, const int* in_sizes, int n_in,
                              void* d_out, int out_size){
    const float* x     = (const float*)d_in[0];
    const float* pe    = (const float*)d_in[1];
    const float* qkv_w = (const float*)d_in[2];
    const float* qkv_b = (const float*)d_in[3];
    const float* lp1_w = (const float*)d_in[4];
    const float* lp1_b = (const float*)d_in[5];
    const float* lp2_w = (const float*)d_in[6];
    const float* lp2_b = (const float*)d_in[7];
    const float* mod1_w= (const float*)d_in[8];
    const float* mod1_b= (const float*)d_in[9];
    const float* mod2_w= (const float*)d_in[10];
    const float* mod2_b= (const float*)d_in[11];
    // d_in[12..16] (pa_w, pa_b, R6_d/h/w) are mathematically dead:
    //   pos_attn adds a per-row constant under softmax; R is orthogonal so q.k is invariant.
    const float* proj_w= (const float*)d_in[17];
    const float* proj_b= (const float*)d_in[18];
    float* out = (float*)d_out;

    prep_w27 <<<(27*96*96+255)/256, 256>>>(lp1_w);
    prep_fold<<<(96*96+255)/256,    256>>>(mod1_w, lp2_w, lp2_b, mod1_b);
    prep_trans<<<(96*288+255)/256,  256>>>(mod2_w, qkv_w, proj_w);

    // t1 = conv3(pos_emb) -> buf0
    conv3_kernel<<<dim3(20,40,BB), 96>>>(pe, lp1_b);
    in_stats<0,1><<<BB*CC, 256>>>();
    // u = Wc @ gelu(IN(t1)) + bc -> buf1
    gemm_kernel<1,0,0,0,1,1,1><<<dim3(500,1,BB), 192>>>(96, nullptr, nullptr, nullptr);
    in_stats<1,2><<<BB*CC, 256>>>();
    // xm = x * sigmoid(mod2 @ gelu(IN(u)) + b) -> buf0 (t1 dead)
    gemm_kernel<1,1,1,1,0,2,0><<<dim3(500,1,BB), 192>>>(96, nullptr, mod2_b, x);
    // qkv = qkv_w @ xm + qkv_b
    gemm_kernel<0,0,2,0,2,0,0><<<dim3(500,3,BB), 192>>>(288, nullptr, qkv_b, nullptr);
    // axial attention, accumulate into buf1 (u dead)
    attn_kernel<0,false><<<dim3(1600,NHD,BB), 128>>>();
    attn_kernel<1,true ><<<dim3(1600,NHD,BB), 128>>>();
    attn_kernel<2,true ><<<dim3(1600,NHD,BB), 128>>>();
    // out = proj @ o + proj_b
    gemm_kernel<0,0,3,1,3,0,0><<<dim3(500,1,BB), 192>>>(96, out, proj_b, nullptr);
}

// round 5
// speedup vs baseline: 1.2056x; 1.1575x over previous
#include <cuda_runtime.h>
#include <math.h>

#define SVOL 64000
#define BB   2
#define CC   96
#define NHD  4
#define HD   24
#define LAX  40

typedef unsigned long long ull;

// ---- scratch: __device__ globals (no allocation anywhere) ----
__device__ float g_buf0[BB*CC*SVOL];   // conv out t1 -> x*mod
__device__ float g_buf1[BB*CC*SVOL];   // u -> attention accumulator
__device__ float g_qkv [BB*288*SVOL];
__device__ float g_pad [(size_t)BB*96*42*42*44];   // circularly padded pos_emb
__device__ float g_mu1[BB*CC], g_rs1[BB*CC], g_mu2[BB*CC], g_rs2[BB*CC];
__device__ float g_W27  [27*96*96];
__device__ float g_WcT  [96*96];
__device__ float g_bc   [96];
__device__ float g_mod2T[96*96];
__device__ float g_qkvT [96*288];
__device__ float g_projT[96*96];

__device__ __forceinline__ float gelu_f(float v){
    return 0.5f*v*(1.0f + erff(v*0.70710678118654752f));
}
__device__ __forceinline__ ull pack_dup(float x){
    ull r; asm("mov.b64 %0, {%1, %1};" : "=l"(r) : "f"(x)); return r;
}
__device__ __forceinline__ void fma2(ull& d, ull a, ull b){
    asm("fma.rn.f32x2 %0, %1, %2, %0;" : "+l"(d) : "l"(a), "l"(b));
}
__device__ __forceinline__ void unpack2(float& lo, float& hi, ull v){
    asm("mov.b64 {%0, %1}, %2;" : "=f"(lo), "=f"(hi) : "l"(v));
}

// ---- weight / input prep ----
__global__ void prep_w27(const float* __restrict__ lp1_w){
    int tid = blockIdx.x*blockDim.x + threadIdx.x;
    if (tid < 27*96*96){
        int t = tid/(96*96); int r = tid%(96*96); int ic = r/96; int oc = r%96;
        g_W27[tid] = lp1_w[(oc*96+ic)*27 + t];
    }
}
__global__ void prep_pad(const float* __restrict__ pe){
    size_t idx = (size_t)blockIdx.x*256 + threadIdx.x;
    if (idx >= (size_t)BB*96*42*42*44) return;
    int pw = (int)(idx % 44); size_t r = idx/44;
    int ph = (int)(r % 42); r /= 42;
    int pd = (int)(r % 42); r /= 42;
    int c  = (int)(r % 96); int b = (int)(r/96);
    int d = (pd+39)%40, h = (ph+39)%40, w = (pw+39)%40;
    g_pad[idx] = pe[(size_t)(b*96+c)*SVOL + d*1600 + h*40 + w];
}
__global__ void prep_fold(const float* __restrict__ mod1_w, const float* __restrict__ lp2_w,
                          const float* __restrict__ lp2_b, const float* __restrict__ mod1_b){
    int tid = blockIdx.x*blockDim.x + threadIdx.x;
    if (tid < 96*96){
        int k = tid/96, m = tid%96;
        float s = 0.f;
        for (int o = 0; o < 96; o++) s += mod1_w[m*96+o]*lp2_w[o*96+k];
        g_WcT[k*96+m] = s;
        if (k == 0){
            float b2 = 0.f;
            for (int o = 0; o < 96; o++) b2 += mod1_w[m*96+o]*lp2_b[o];
            g_bc[m] = b2 + mod1_b[m];
        }
    }
}
__global__ void prep_trans(const float* __restrict__ mod2_w, const float* __restrict__ qkv_w,
                           const float* __restrict__ proj_w){
    int tid = blockIdx.x*blockDim.x + threadIdx.x;
    if (tid < 96*96){
        int k = tid/96, m = tid%96;
        g_mod2T[k*96+m] = mod2_w[m*96+k];
        g_projT[k*96+m] = proj_w[m*96+k];
    }
    if (tid < 96*288){
        int k = tid/288, m = tid%288;
        g_qkvT[k*288+m] = qkv_w[m*96+k];
    }
}

// ---- conv3x3x3 circular, f32x2 packed over oc pairs, padded input ----
// smem: Xs[16 ic][4 rows][44] = 11.3KB, Ws3[3 dx][16 ic][96 oc] = 18.4KB
__global__ __launch_bounds__(96) void conv3_kernel(const float* __restrict__ lp1_b){
    __shared__ float Xs [16*4*44];
    __shared__ float Ws3[3*16*96];
    int b = blockIdx.z, d = blockIdx.y, h0 = blockIdx.x*2;
    int tid = threadIdx.x;
    int tm = tid/8, tn = tid%8;       // tm: oc-octet 0..11, tn: col group 0..7
    int cb = tn*10;
    int g  = cb/40;                   // output row within 2-row tile
    int wb = cb%40;

    ull acc2[4][10];
    #pragma unroll
    for (int i=0;i<4;i++)
        #pragma unroll
        for (int j=0;j<10;j++) acc2[i][j] = 0ULL;

    for (int dz=0; dz<3; dz++){
        int pd = d + dz;              // padded depth index
        for (int kc=0; kc<6; kc++){
            __syncthreads();
            // stage Xs: 64 rows (16 ic x 4 padded h-rows) x 11 float4, contiguous
            for (int idx=tid; idx<704; idx+=96){
                int row = idx/11, q = idx - row*11;
                int ic = row>>2, rr = row&3;
                size_t src = (((size_t)(b*96 + kc*16 + ic)*42 + pd)*42 + (h0+rr))*44 + q*4;
                *reinterpret_cast<float4*>(&Xs[(ic*4+rr)*44 + q*4]) =
                    *reinterpret_cast<const float4*>(&g_pad[src]);
            }
            for (int dy=0; dy<3; dy++){
                int t0 = (dz*3+dy)*3;
                __syncthreads();
                for (int idx=tid; idx<1152; idx+=96){
                    int dx = idx/384, rr = idx - dx*384;
                    *reinterpret_cast<float4*>(&Ws3[dx*1536 + rr*4]) =
                        *reinterpret_cast<const float4*>(&g_W27[(size_t)(t0+dx)*9216 + kc*16*96 + rr*4]);
                }
                __syncthreads();
                for (int k=0;k<16;k++){
                    ull xp[12];
                    #pragma unroll
                    for (int l=0;l<12;l++)
                        xp[l] = pack_dup(Xs[(k*4 + g + dy)*44 + wb + l]);
                    #pragma unroll
                    for (int dx=0;dx<3;dx++){
                        const ull* wp = reinterpret_cast<const ull*>(&Ws3[dx*1536 + k*96 + tm*8]);
                        ull w2[4];
                        #pragma unroll
                        for (int i=0;i<4;i++) w2[i] = wp[i];
                        #pragma unroll
                        for (int i=0;i<4;i++)
                            #pragma unroll
                            for (int j=0;j<10;j++)
                                fma2(acc2[i][j], w2[i], xp[j+dx]);
                    }
                }
            }
        }
    }
    size_t obase = (size_t)b*CC*SVOL + d*1600 + (h0+g)*40 + wb;
    #pragma unroll
    for (int i=0;i<4;i++){
        int oc0 = tm*8 + 2*i;
        float b0 = lp1_b[oc0], b1 = lp1_b[oc0+1];
        #pragma unroll
        for (int j=0;j<10;j++){
            float lo, hi; unpack2(lo, hi, acc2[i][j]);
            g_buf0[obase + (size_t)oc0*SVOL + j]     = lo + b0;
            g_buf0[obase + (size_t)(oc0+1)*SVOL + j] = hi + b1;
        }
    }
}

// ---- per-(b,c) instance-norm stats ----
template<int SRC, int SET>
__global__ __launch_bounds__(256) void in_stats(){
    const float* src = (SRC==0) ? g_buf0 : g_buf1;
    float* mu = (SET==1) ? g_mu1 : g_mu2;
    float* rs = (SET==1) ? g_rs1 : g_rs2;
    int bc = blockIdx.x;
    const float* p = src + (size_t)bc*SVOL;
    float s=0.f, s2=0.f;
    for (int i=threadIdx.x; i<SVOL/4; i+=256){
        float4 v = reinterpret_cast<const float4*>(p)[i];
        s += v.x+v.y+v.z+v.w;
        s2 = fmaf(v.x,v.x,s2); s2 = fmaf(v.y,v.y,s2);
        s2 = fmaf(v.z,v.z,s2); s2 = fmaf(v.w,v.w,s2);
    }
    __shared__ float r1[256], r2[256];
    r1[threadIdx.x]=s; r2[threadIdx.x]=s2;
    __syncthreads();
    for (int off=128; off>0; off>>=1){
        if (threadIdx.x<off){ r1[threadIdx.x]+=r1[threadIdx.x+off]; r2[threadIdx.x]+=r2[threadIdx.x+off]; }
        __syncthreads();
    }
    if (threadIdx.x==0){
        float m = r1[0]*(1.0f/SVOL);
        float var = r2[0]*(1.0f/SVOL) - m*m;
        mu[bc]=m; rs[bc]=rsqrtf(var + 1e-5f);
    }
}

// ---- fused 1x1-conv GEMM, f32x2 packed over m pairs ----
template<int PRO, int EPI, int AW, int SRC, int DST, int SET, int BIASG>
__global__ __launch_bounds__(192) void gemm_kernel(
    int Mtotal, float* __restrict__ extY,
    const float* __restrict__ bias_ext,
    const float* __restrict__ gate)
{
    __shared__ float As[48*96];
    __shared__ float Xs[48*128];
    const float* AT = (AW==0) ? g_WcT : (AW==1) ? g_mod2T : (AW==2) ? g_qkvT : g_projT;
    const float* X  = (SRC==0) ? g_buf0 : g_buf1;
    float* Y = (DST==0) ? g_buf0 : (DST==1) ? g_buf1 : (DST==2) ? g_qkv : extY;
    const float* bias = (BIASG==1) ? g_bc : bias_ext;
    const float* mu = (SET==1) ? g_mu1 : g_mu2;
    const float* rs = (SET==1) ? g_rs1 : g_rs2;

    int b = blockIdx.z, m0 = blockIdx.y*96, n0 = blockIdx.x*128;
    int tid = threadIdx.x, tm = tid/16, tn = tid%16;   // 12 x 16
    const float* xb = X + (size_t)b*96*SVOL + n0;

    ull acc2[4][8];
    #pragma unroll
    for (int i=0;i<4;i++)
        #pragma unroll
        for (int j=0;j<8;j++) acc2[i][j]=0ULL;

    for (int kc=0; kc<2; kc++){
        __syncthreads();
        for (int idx=tid; idx<1152; idx+=192){
            int k = idx/24, mq = idx%24;
            *reinterpret_cast<float4*>(&As[k*96 + mq*4]) =
                *reinterpret_cast<const float4*>(&AT[(kc*48+k)*Mtotal + m0 + mq*4]);
        }
        for (int idx=tid; idx<1536; idx+=192){
            int k = idx/32, cq = idx%32;
            int kg = kc*48 + k;
            float4 v = *reinterpret_cast<const float4*>(&xb[(size_t)kg*SVOL + cq*4]);
            if (PRO==1){
                float m = mu[b*96+kg], r = rs[b*96+kg];
                v.x = gelu_f((v.x-m)*r); v.y = gelu_f((v.y-m)*r);
                v.z = gelu_f((v.z-m)*r); v.w = gelu_f((v.w-m)*r);
            }
            *reinterpret_cast<float4*>(&Xs[k*128 + cq*4]) = v;
        }
        __syncthreads();
        for (int k=0;k<48;k++){
            const ull* wp = reinterpret_cast<const ull*>(&As[k*96 + tm*8]);
            ull w2[4];
            #pragma unroll
            for (int i=0;i<4;i++) w2[i] = wp[i];
            float4 x0 = *reinterpret_cast<const float4*>(&Xs[k*128 + tn*8]);
            float4 x1 = *reinterpret_cast<const float4*>(&Xs[k*128 + tn*8 + 4]);
            ull xp[8] = { pack_dup(x0.x), pack_dup(x0.y), pack_dup(x0.z), pack_dup(x0.w),
                          pack_dup(x1.x), pack_dup(x1.y), pack_dup(x1.z), pack_dup(x1.w) };
            #pragma unroll
            for (int i=0;i<4;i++)
                #pragma unroll
                for (int j=0;j<8;j++) fma2(acc2[i][j], w2[i], xp[j]);
        }
    }

    #pragma unroll
    for (int i=0;i<4;i++){
        int m = m0 + tm*8 + 2*i;
        float bi0 = bias[m], bi1 = bias[m+1];
        #pragma unroll
        for (int j=0;j<8;j++){
            int col = n0 + tn*8 + j;
            float lo, hi; unpack2(lo, hi, acc2[i][j]);
            float r0 = lo + bi0, r1 = hi + bi1;
            if (EPI==1){
                float g0 = gate[((size_t)b*96 + m  )*SVOL + col];
                float g1 = gate[((size_t)b*96 + m+1)*SVOL + col];
                r0 = g0 * (1.0f/(1.0f + __expf(-r0)));
                r1 = g1 * (1.0f/(1.0f + __expf(-r1)));
            }
            Y[((size_t)b*Mtotal + m  )*SVOL + col] = r0;
            Y[((size_t)b*Mtotal + m+1)*SVOL + col] = r1;
        }
    }
}

// ---- axial attention (rotation + pos_attn mathematically eliminated); out -> g_buf1 ----
template<int AXIS, bool ACCUM>
__global__ __launch_bounds__(128) void attn_kernel(){
    __shared__ float qs[HD][LAX];
    __shared__ float ks[HD][LAX];
    __shared__ float vs[LAX][HD];
    __shared__ float ps[LAX][LAX];
    int line = blockIdx.x, head = blockIdx.y, b = blockIdx.z;
    int tid = threadIdx.x;
    int s0 = 0, stride = 1;
    if (AXIS==0){ int d=line/40, h=line%40; s0 = d*1600 + h*40; stride = 1;    }
    if (AXIS==1){ int d=line/40, w=line%40; s0 = d*1600 + w;    stride = 40;   }
    if (AXIS==2){ int h=line/40, w=line%40; s0 = h*40 + w;      stride = 1600; }
    const float* base = g_qkv + (size_t)b*288*SVOL;

    for (int idx=tid; idx<2*HD*LAX; idx+=128){
        int t = idx/960, r = idx%960, hd = r/40, l = r%40;
        float v = base[(size_t)((t*NHD+head)*HD + hd)*SVOL + s0 + l*stride];
        if (t==0) qs[hd][l]=v; else ks[hd][l]=v;
    }
    for (int idx=tid; idx<HD*LAX; idx+=128){
        int hd = idx/40, l = idx%40;
        vs[l][hd] = base[(size_t)((2*NHD+head)*HD + hd)*SVOL + s0 + l*stride];
    }
    __syncthreads();

    const float scale = 0.2041241452319315f;  // 24^-0.5
    for (int idx=tid; idx<400; idx+=128){
        int i = idx/10, j0 = (idx%10)*4;
        float a0=0.f,a1=0.f,a2=0.f,a3=0.f;
        #pragma unroll
        for (int hd=0; hd<HD; hd++){
            float qv = qs[hd][i];
            float4 kv = *reinterpret_cast<const float4*>(&ks[hd][j0]);
            a0 = fmaf(qv,kv.x,a0); a1 = fmaf(qv,kv.y,a1);
            a2 = fmaf(qv,kv.z,a2); a3 = fmaf(qv,kv.w,a3);
        }
        ps[i][j0+0]=a0*scale; ps[i][j0+1]=a1*scale;
        ps[i][j0+2]=a2*scale; ps[i][j0+3]=a3*scale;
    }
    __syncthreads();
    if (tid < 40){
        float mx = -1e30f;
        for (int j=0;j<40;j++) mx = fmaxf(mx, ps[tid][j]);
        float sum = 0.f;
        for (int j=0;j<40;j++){ float e = __expf(ps[tid][j]-mx); ps[tid][j]=e; sum+=e; }
        float inv = 1.0f/sum;
        for (int j=0;j<40;j++) ps[tid][j]*=inv;
    }
    __syncthreads();
    for (int idx=tid; idx<240; idx+=128){
        int i = idx/6, hd0 = (idx%6)*4;
        float a0=0.f,a1=0.f,a2=0.f,a3=0.f;
        #pragma unroll
        for (int j=0;j<40;j++){
            float pv = ps[i][j];
            float4 vv = *reinterpret_cast<const float4*>(&vs[j][hd0]);
            a0 = fmaf(pv,vv.x,a0); a1 = fmaf(pv,vv.y,a1);
            a2 = fmaf(pv,vv.z,a2); a3 = fmaf(pv,vv.w,a3);
        }
        float r[4] = {a0,a1,a2,a3};
        #pragma unroll
        for (int q=0;q<4;q++){
            size_t oi = ((size_t)b*CC + head*HD + hd0 + q)*SVOL + s0 + i*stride;
            if (ACCUM) g_buf1[oi] += r[q]; else g_buf1[oi] = r[q];
        }
    }
}

extern "C" void kernel_launch(void* const* d_in, const int* in_sizes, int n_in,
                              void* d_out, int out_size){
    const float* x     = (const float*)d_in[0];
    const float* pe    = (const float*)d_in[1];
    const float* qkv_w = (const float*)d_in[2];
    const float* qkv_b = (const float*)d_in[3];
    const float* lp1_w = (const float*)d_in[4];
    const float* lp1_b = (const float*)d_in[5];
    const float* lp2_w = (const float*)d_in[6];
    const float* lp2_b = (const float*)d_in[7];
    const float* mod1_w= (const float*)d_in[8];
    const float* mod1_b= (const float*)d_in[9];
    const float* mod2_w= (const float*)d_in[10];
    const float* mod2_b= (const float*)d_in[11];
    // d_in[12..16] (pa_w, pa_b, R6_d/h/w) are mathematically dead:
    //   pos_attn adds a per-row constant under softmax; R is orthogonal so q.k is invariant.
    const float* proj_w= (const float*)d_in[17];
    const float* proj_b= (const float*)d_in[18];
    float* out = (float*)d_out;

    prep_w27 <<<(27*96*96+255)/256, 256>>>(lp1_w);
    prep_pad <<<(int)(((size_t)BB*96*42*42*44 + 255)/256), 256>>>(pe);
    prep_fold<<<(96*96+255)/256,    256>>>(mod1_w, lp2_w, lp2_b, mod1_b);
    prep_trans<<<(96*288+255)/256,  256>>>(mod2_w, qkv_w, proj_w);

    // t1 = conv3(pos_emb) -> buf0
    conv3_kernel<<<dim3(20,40,BB), 96>>>(lp1_b);
    in_stats<0,1><<<BB*CC, 256>>>();
    // u = Wc @ gelu(IN(t1)) + bc -> buf1
    gemm_kernel<1,0,0,0,1,1,1><<<dim3(500,1,BB), 192>>>(96, nullptr, nullptr, nullptr);
    in_stats<1,2><<<BB*CC, 256>>>();
    // xm = x * sigmoid(mod2 @ gelu(IN(u)) + b) -> buf0 (t1 dead)
    gemm_kernel<1,1,1,1,0,2,0><<<dim3(500,1,BB), 192>>>(96, nullptr, mod2_b, x);
    // qkv = qkv_w @ xm + qkv_b
    gemm_kernel<0,0,2,0,2,0,0><<<dim3(500,3,BB), 192>>>(288, nullptr, qkv_b, nullptr);
    // axial attention, accumulate into buf1 (u dead)
    attn_kernel<0,false><<<dim3(1600,NHD,BB), 128>>>();
    attn_kernel<1,true ><<<dim3(1600,NHD,BB), 128>>>();
    attn_kernel<2,true ><<<dim3(1600,NHD,BB), 128>>>();
    // out = proj @ o + proj_b
    gemm_kernel<0,0,3,1,3,0,0><<<dim3(500,1,BB), 192>>>(96, out, proj_b, nullptr);
}

// round 7
// speedup vs baseline: 1.2117x; 1.0051x over previous
#include <cuda_runtime.h>
#include <math.h>

#define SVOL 64000
#define BB   2
#define CC   96
#define NHD  4
#define HD   24
#define LAX  40

typedef unsigned long long ull;

// ---- scratch: __device__ globals (no allocation anywhere) ----
__device__ float g_buf0[BB*CC*SVOL];   // conv out t1 -> x*mod
__device__ float g_buf1[BB*CC*SVOL];   // u -> attention accumulator
__device__ float g_qkv [BB*288*SVOL];
__device__ float g_pad [(size_t)BB*96*42*42*44];   // circularly padded pos_emb
__device__ float g_mu1[BB*CC], g_rs1[BB*CC], g_mu2[BB*CC], g_rs2[BB*CC];
__device__ float g_W27  [27*96*96];
__device__ float g_WcT  [96*96];
__device__ float g_bc   [96];
__device__ float g_mod2T[96*96];
__device__ float g_qkvT [96*288];
__device__ float g_projT[96*96];

__device__ __forceinline__ float gelu_f(float v){
    return 0.5f*v*(1.0f + erff(v*0.70710678118654752f));
}
__device__ __forceinline__ ull pack_dup(float x){
    ull r; asm("mov.b64 %0, {%1, %1};" : "=l"(r) : "f"(x)); return r;
}
__device__ __forceinline__ void fma2(ull& d, ull a, ull b){
    asm("fma.rn.f32x2 %0, %1, %2, %0;" : "+l"(d) : "l"(a), "l"(b));
}
__device__ __forceinline__ void unpack2(float& lo, float& hi, ull v){
    asm("mov.b64 {%0, %1}, %2;" : "=f"(lo), "=f"(hi) : "l"(v));
}

// ---- weight / input prep ----
__global__ void prep_w27(const float* __restrict__ lp1_w){
    int tid = blockIdx.x*blockDim.x + threadIdx.x;
    if (tid < 27*96*96){
        int t = tid/(96*96); int r = tid%(96*96); int ic = r/96; int oc = r%96;
        g_W27[tid] = lp1_w[(oc*96+ic)*27 + t];
    }
}
__global__ void prep_pad(const float* __restrict__ pe){
    size_t idx = (size_t)blockIdx.x*256 + threadIdx.x;
    if (idx >= (size_t)BB*96*42*42*44) return;
    int pw = (int)(idx % 44); size_t r = idx/44;
    int ph = (int)(r % 42); r /= 42;
    int pd = (int)(r % 42); r /= 42;
    int c  = (int)(r % 96); int b = (int)(r/96);
    int d = (pd+39)%40, h = (ph+39)%40, w = (pw+39)%40;
    g_pad[idx] = pe[(size_t)(b*96+c)*SVOL + d*1600 + h*40 + w];
}
__global__ void prep_fold(const float* __restrict__ mod1_w, const float* __restrict__ lp2_w,
                          const float* __restrict__ lp2_b, const float* __restrict__ mod1_b){
    int tid = blockIdx.x*blockDim.x + threadIdx.x;
    if (tid < 96*96){
        int k = tid/96, m = tid%96;
        float s = 0.f;
        for (int o = 0; o < 96; o++) s += mod1_w[m*96+o]*lp2_w[o*96+k];
        g_WcT[k*96+m] = s;
        if (k == 0){
            float b2 = 0.f;
            for (int o = 0; o < 96; o++) b2 += mod1_w[m*96+o]*lp2_b[o];
            g_bc[m] = b2 + mod1_b[m];
        }
    }
}
__global__ void prep_trans(const float* __restrict__ mod2_w, const float* __restrict__ qkv_w,
                           const float* __restrict__ proj_w){
    int tid = blockIdx.x*blockDim.x + threadIdx.x;
    if (tid < 96*96){
        int k = tid/96, m = tid%96;
        g_mod2T[k*96+m] = mod2_w[m*96+k];
        g_projT[k*96+m] = proj_w[m*96+k];
    }
    if (tid < 96*288){
        int k = tid/288, m = tid%288;
        g_qkvT[k*288+m] = qkv_w[m*96+k];
    }
}

// ---- conv3x3x3 circular, f32x2 packed over oc pairs, padded input ----
// smem: Xs[16 ic][4 rows][44] = 11.3KB, Ws3[3 dx][16 ic][96 oc] = 18.4KB
__global__ __launch_bounds__(96) void conv3_kernel(const float* __restrict__ lp1_b){
    __shared__ float Xs [16*4*44];
    __shared__ float Ws3[3*16*96];
    int b = blockIdx.z, d = blockIdx.y, h0 = blockIdx.x*2;
    int tid = threadIdx.x;
    int tm = tid/8, tn = tid%8;       // tm: oc-octet 0..11, tn: col group 0..7
    int cb = tn*10;
    int g  = cb/40;                   // output row within 2-row tile
    int wb = cb%40;

    ull acc2[4][10];
    #pragma unroll
    for (int i=0;i<4;i++)
        #pragma unroll
        for (int j=0;j<10;j++) acc2[i][j] = 0ULL;

    for (int dz=0; dz<3; dz++){
        int pd = d + dz;              // padded depth index
        for (int kc=0; kc<6; kc++){
            __syncthreads();
            // stage Xs: 64 rows (16 ic x 4 padded h-rows) x 11 float4, contiguous
            for (int idx=tid; idx<704; idx+=96){
                int row = idx/11, q = idx - row*11;
                int ic = row>>2, rr = row&3;
                size_t src = (((size_t)(b*96 + kc*16 + ic)*42 + pd)*42 + (h0+rr))*44 + q*4;
                *reinterpret_cast<float4*>(&Xs[(ic*4+rr)*44 + q*4]) =
                    *reinterpret_cast<const float4*>(&g_pad[src]);
            }
            for (int dy=0; dy<3; dy++){
                int t0 = (dz*3+dy)*3;
                __syncthreads();
                for (int idx=tid; idx<1152; idx+=96){
                    int dx = idx/384, rr = idx - dx*384;
                    *reinterpret_cast<float4*>(&Ws3[dx*1536 + rr*4]) =
                        *reinterpret_cast<const float4*>(&g_W27[(size_t)(t0+dx)*9216 + kc*16*96 + rr*4]);
                }
                __syncthreads();
                for (int k=0;k<16;k++){
                    ull xp[12];
                    #pragma unroll
                    for (int l=0;l<12;l++)
                        xp[l] = pack_dup(Xs[(k*4 + g + dy)*44 + wb + l]);
                    #pragma unroll
                    for (int dx=0;dx<3;dx++){
                        const ull* wp = reinterpret_cast<const ull*>(&Ws3[dx*1536 + k*96 + tm*8]);
                        ull w2[4];
                        #pragma unroll
                        for (int i=0;i<4;i++) w2[i] = wp[i];
                        #pragma unroll
                        for (int i=0;i<4;i++)
                            #pragma unroll
                            for (int j=0;j<10;j++)
                                fma2(acc2[i][j], w2[i], xp[j+dx]);
                    }
                }
            }
        }
    }
    size_t obase = (size_t)b*CC*SVOL + d*1600 + (h0+g)*40 + wb;
    #pragma unroll
    for (int i=0;i<4;i++){
        int oc0 = tm*8 + 2*i;
        float b0 = lp1_b[oc0], b1 = lp1_b[oc0+1];
        #pragma unroll
        for (int j=0;j<10;j++){
            float lo, hi; unpack2(lo, hi, acc2[i][j]);
            g_buf0[obase + (size_t)oc0*SVOL + j]     = lo + b0;
            g_buf0[obase + (size_t)(oc0+1)*SVOL + j] = hi + b1;
        }
    }
}

// ---- per-(b,c) instance-norm stats ----
template<int SRC, int SET>
__global__ __launch_bounds__(256) void in_stats(){
    const float* src = (SRC==0) ? g_buf0 : g_buf1;
    float* mu = (SET==1) ? g_mu1 : g_mu2;
    float* rs = (SET==1) ? g_rs1 : g_rs2;
    int bc = blockIdx.x;
    const float* p = src + (size_t)bc*SVOL;
    float s=0.f, s2=0.f;
    for (int i=threadIdx.x; i<SVOL/4; i+=256){
        float4 v = reinterpret_cast<const float4*>(p)[i];
        s += v.x+v.y+v.z+v.w;
        s2 = fmaf(v.x,v.x,s2); s2 = fmaf(v.y,v.y,s2);
        s2 = fmaf(v.z,v.z,s2); s2 = fmaf(v.w,v.w,s2);
    }
    __shared__ float r1[256], r2[256];
    r1[threadIdx.x]=s; r2[threadIdx.x]=s2;
    __syncthreads();
    for (int off=128; off>0; off>>=1){
        if (threadIdx.x<off){ r1[threadIdx.x]+=r1[threadIdx.x+off]; r2[threadIdx.x]+=r2[threadIdx.x+off]; }
        __syncthreads();
    }
    if (threadIdx.x==0){
        float m = r1[0]*(1.0f/SVOL);
        float var = r2[0]*(1.0f/SVOL) - m*m;
        mu[bc]=m; rs[bc]=rsqrtf(var + 1e-5f);
    }
}

// ---- fused 1x1-conv GEMM, f32x2 packed over m pairs ----
template<int PRO, int EPI, int AW, int SRC, int DST, int SET, int BIASG>
__global__ __launch_bounds__(192) void gemm_kernel(
    int Mtotal, float* __restrict__ extY,
    const float* __restrict__ bias_ext,
    const float* __restrict__ gate)
{
    __shared__ float As[48*96];
    __shared__ float Xs[48*128];
    const float* AT = (AW==0) ? g_WcT : (AW==1) ? g_mod2T : (AW==2) ? g_qkvT : g_projT;
    const float* X  = (SRC==0) ? g_buf0 : g_buf1;
    float* Y = (DST==0) ? g_buf0 : (DST==1) ? g_buf1 : (DST==2) ? g_qkv : extY;
    const float* bias = (BIASG==1) ? g_bc : bias_ext;
    const float* mu = (SET==1) ? g_mu1 : g_mu2;
    const float* rs = (SET==1) ? g_rs1 : g_rs2;

    int b = blockIdx.z, m0 = blockIdx.y*96, n0 = blockIdx.x*128;
    int tid = threadIdx.x, tm = tid/16, tn = tid%16;   // 12 x 16
    const float* xb = X + (size_t)b*96*SVOL + n0;

    ull acc2[4][8];
    #pragma unroll
    for (int i=0;i<4;i++)
        #pragma unroll
        for (int j=0;j<8;j++) acc2[i][j]=0ULL;

    for (int kc=0; kc<2; kc++){
        __syncthreads();
        for (int idx=tid; idx<1152; idx+=192){
            int k = idx/24, mq = idx%24;
            *reinterpret_cast<float4*>(&As[k*96 + mq*4]) =
                *reinterpret_cast<const float4*>(&AT[(kc*48+k)*Mtotal + m0 + mq*4]);
        }
        for (int idx=tid; idx<1536; idx+=192){
            int k = idx/32, cq = idx%32;
            int kg = kc*48 + k;
            float4 v = *reinterpret_cast<const float4*>(&xb[(size_t)kg*SVOL + cq*4]);
            if (PRO==1){
                float m = mu[b*96+kg], r = rs[b*96+kg];
                v.x = gelu_f((v.x-m)*r); v.y = gelu_f((v.y-m)*r);
                v.z = gelu_f((v.z-m)*r); v.w = gelu_f((v.w-m)*r);
            }
            *reinterpret_cast<float4*>(&Xs[k*128 + cq*4]) = v;
        }
        __syncthreads();
        for (int k=0;k<48;k++){
            const ull* wp = reinterpret_cast<const ull*>(&As[k*96 + tm*8]);
            ull w2[4];
            #pragma unroll
            for (int i=0;i<4;i++) w2[i] = wp[i];
            float4 x0 = *reinterpret_cast<const float4*>(&Xs[k*128 + tn*8]);
            float4 x1 = *reinterpret_cast<const float4*>(&Xs[k*128 + tn*8 + 4]);
            ull xp[8] = { pack_dup(x0.x), pack_dup(x0.y), pack_dup(x0.z), pack_dup(x0.w),
                          pack_dup(x1.x), pack_dup(x1.y), pack_dup(x1.z), pack_dup(x1.w) };
            #pragma unroll
            for (int i=0;i<4;i++)
                #pragma unroll
                for (int j=0;j<8;j++) fma2(acc2[i][j], w2[i], xp[j]);
        }
    }

    #pragma unroll
    for (int i=0;i<4;i++){
        int m = m0 + tm*8 + 2*i;
        float bi0 = bias[m], bi1 = bias[m+1];
        #pragma unroll
        for (int j=0;j<8;j++){
            int col = n0 + tn*8 + j;
            float lo, hi; unpack2(lo, hi, acc2[i][j]);
            float r0 = lo + bi0, r1 = hi + bi1;
            if (EPI==1){
                float g0 = gate[((size_t)b*96 + m  )*SVOL + col];
                float g1 = gate[((size_t)b*96 + m+1)*SVOL + col];
                r0 = g0 * (1.0f/(1.0f + __expf(-r0)));
                r1 = g1 * (1.0f/(1.0f + __expf(-r1)));
            }
            Y[((size_t)b*Mtotal + m  )*SVOL + col] = r0;
            Y[((size_t)b*Mtotal + m+1)*SVOL + col] = r1;
        }
    }
}

// ---- axial attention (rotation + pos_attn mathematically eliminated); out -> g_buf1 ----
template<int AXIS, bool ACCUM>
__global__ __launch_bounds__(128) void attn_kernel(){
    __shared__ float qs[HD][LAX];
    __shared__ float ks[HD][LAX];
    __shared__ float vs[LAX][HD];
    __shared__ float ps[LAX][LAX];
    int line = blockIdx.x, head = blockIdx.y, b = blockIdx.z;
    int tid = threadIdx.x;
    int s0 = 0, stride = 1;
    if (AXIS==0){ int d=line/40, h=line%40; s0 = d*1600 + h*40; stride = 1;    }
    if (AXIS==1){ int d=line/40, w=line%40; s0 = d*1600 + w;    stride = 40;   }
    if (AXIS==2){ int h=line/40, w=line%40; s0 = h*40 + w;      stride = 1600; }
    const float* base = g_qkv + (size_t)b*288*SVOL;

    for (int idx=tid; idx<2*HD*LAX; idx+=128){
        int t = idx/960, r = idx%960, hd = r/40, l = r%40;
        float v = base[(size_t)((t*NHD+head)*HD + hd)*SVOL + s0 + l*stride];
        if (t==0) qs[hd][l]=v; else ks[hd][l]=v;
    }
    for (int idx=tid; idx<HD*LAX; idx+=128){
        int hd = idx/40, l = idx%40;
        vs[l][hd] = base[(size_t)((2*NHD+head)*HD + hd)*SVOL + s0 + l*stride];
    }
    __syncthreads();

    const float scale = 0.2041241452319315f;  // 24^-0.5
    for (int idx=tid; idx<400; idx+=128){
        int i = idx/10, j0 = (idx%10)*4;
        float a0=0.f,a1=0.f,a2=0.f,a3=0.f;
        #pragma unroll
        for (int hd=0; hd<HD; hd++){
            float qv = qs[hd][i];
            float4 kv = *reinterpret_cast<const float4*>(&ks[hd][j0]);
            a0 = fmaf(qv,kv.x,a0); a1 = fmaf(qv,kv.y,a1);
            a2 = fmaf(qv,kv.z,a2); a3 = fmaf(qv,kv.w,a3);
        }
        ps[i][j0+0]=a0*scale; ps[i][j0+1]=a1*scale;
        ps[i][j0+2]=a2*scale; ps[i][j0+3]=a3*scale;
    }
    __syncthreads();
    if (tid < 40){
        float mx = -1e30f;
        for (int j=0;j<40;j++) mx = fmaxf(mx, ps[tid][j]);
        float sum = 0.f;
        for (int j=0;j<40;j++){ float e = __expf(ps[tid][j]-mx); ps[tid][j]=e; sum+=e; }
        float inv = 1.0f/sum;
        for (int j=0;j<40;j++) ps[tid][j]*=inv;
    }
    __syncthreads();
    for (int idx=tid; idx<240; idx+=128){
        int i = idx/6, hd0 = (idx%6)*4;
        float a0=0.f,a1=0.f,a2=0.f,a3=0.f;
        #pragma unroll
        for (int j=0;j<40;j++){
            float pv = ps[i][j];
            float4 vv = *reinterpret_cast<const float4*>(&vs[j][hd0]);
            a0 = fmaf(pv,vv.x,a0); a1 = fmaf(pv,vv.y,a1);
            a2 = fmaf(pv,vv.z,a2); a3 = fmaf(pv,vv.w,a3);
        }
        float r[4] = {a0,a1,a2,a3};
        #pragma unroll
        for (int q=0;q<4;q++){
            size_t oi = ((size_t)b*CC + head*HD + hd0 + q)*SVOL + s0 + i*stride;
            if (ACCUM) g_buf1[oi] += r[q]; else g_buf1[oi] = r[q];
        }
    }
}

extern "C" void kernel_launch(void* const* d_in, const int* in_sizes, int n_in,
                              void* d_out, int out_size){
    const float* x     = (const float*)d_in[0];
    const float* pe    = (const float*)d_in[1];
    const float* qkv_w = (const float*)d_in[2];
    const float* qkv_b = (const float*)d_in[3];
    const float* lp1_w = (const float*)d_in[4];
    const float* lp1_b = (const float*)d_in[5];
    const float* lp2_w = (const float*)d_in[6];
    const float* lp2_b = (const float*)d_in[7];
    const float* mod1_w= (const float*)d_in[8];
    const float* mod1_b= (const float*)d_in[9];
    const float* mod2_w= (const float*)d_in[10];
    const float* mod2_b= (const float*)d_in[11];
    // d_in[12..16] (pa_w, pa_b, R6_d/h/w) are mathematically dead:
    //   pos_attn adds a per-row constant under softmax; R is orthogonal so q.k is invariant.
    const float* proj_w= (const float*)d_in[17];
    const float* proj_b= (const float*)d_in[18];
    float* out = (float*)d_out;

    prep_w27 <<<(27*96*96+255)/256, 256>>>(lp1_w);
    prep_pad <<<(int)(((size_t)BB*96*42*42*44 + 255)/256), 256>>>(pe);
    prep_fold<<<(96*96+255)/256,    256>>>(mod1_w, lp2_w, lp2_b, mod1_b);
    prep_trans<<<(96*288+255)/256,  256>>>(mod2_w, qkv_w, proj_w);

    // t1 = conv3(pos_emb) -> buf0
    conv3_kernel<<<dim3(20,40,BB), 96>>>(lp1_b);
    in_stats<0,1><<<BB*CC, 256>>>();
    // u = Wc @ gelu(IN(t1)) + bc -> buf1
    gemm_kernel<1,0,0,0,1,1,1><<<dim3(500,1,BB), 192>>>(96, nullptr, nullptr, nullptr);
    in_stats<1,2><<<BB*CC, 256>>>();
    // xm = x * sigmoid(mod2 @ gelu(IN(u)) + b) -> buf0 (t1 dead)
    gemm_kernel<1,1,1,1,0,2,0><<<dim3(500,1,BB), 192>>>(96, nullptr, mod2_b, x);
    // qkv = qkv_w @ xm + qkv_b
    gemm_kernel<0,0,2,0,2,0,0><<<dim3(500,3,BB), 192>>>(288, nullptr, qkv_b, nullptr);
    // axial attention, accumulate into buf1 (u dead)
    attn_kernel<0,false><<<dim3(1600,NHD,BB), 128>>>();
    attn_kernel<1,true ><<<dim3(1600,NHD,BB), 128>>>();
    attn_kernel<2,true ><<<dim3(1600,NHD,BB), 128>>>();
    // out = proj @ o + proj_b
    gemm_kernel<0,0,3,1,3,0,0><<<dim3(500,1,BB), 192>>>(96, out, proj_b, nullptr);
}